// round 13
// baseline (speedup 1.0000x reference)
#include <cuda_runtime.h>

#define E_TOTAL 20000
#define FDIM 17
#define HDIM 32
#define TILE_E 128
#define LN_EPS 1e-5f

__device__ float g_h[E_TOTAL * HDIM];

// ---------- packed fp32x2 helpers (Blackwell dual-FP32) ----------
__device__ __forceinline__ unsigned long long pk2(float x, float y) {
    unsigned long long r;
    asm("mov.b64 %0, {%1, %2};" : "=l"(r) : "f"(x), "f"(y));
    return r;
}
__device__ __forceinline__ void upk2(unsigned long long v, float& x, float& y) {
    asm("mov.b64 {%0, %1}, %2;" : "=f"(x), "=f"(y) : "l"(v));
}
__device__ __forceinline__ void fma2(unsigned long long& d,
                                     unsigned long long a, unsigned long long b) {
    asm("fma.rn.f32x2 %0, %1, %2, %0;" : "+l"(d) : "l"(a), "l"(b));
}

// ---------------------------------------------------------------------------
// Kernel 1: radial MLP  f[E,17] -> h[E,32]   (4 edges per warp)
// ---------------------------------------------------------------------------
__global__ __launch_bounds__(256) void mlp_kernel(
    const float* __restrict__ f,
    const float* __restrict__ w1, const float* __restrict__ b1,
    const float* __restrict__ g1, const float* __restrict__ be1,
    const float* __restrict__ w2, const float* __restrict__ b2,
    const float* __restrict__ g2, const float* __restrict__ be2)
{
    const int tid  = threadIdx.x;
    const int warp = tid >> 5;
    const int lane = tid & 31;

    __shared__ float w1s[32 * FDIM];
    __shared__ float w2s[32 * 33];
    __shared__ float sf[8][FDIM];
    __shared__ float sh[8][HDIM];

    for (int i = tid; i < 32 * FDIM; i += 256) w1s[i] = w1[i];
    for (int i = tid; i < 32 * 32;  i += 256) w2s[(i >> 5) * 33 + (i & 31)] = w2[i];
    __syncthreads();

    const float bb1 = b1[lane], gg1 = g1[lane], bbe1 = be1[lane];
    const float bb2 = b2[lane], gg2 = g2[lane], bbe2 = be2[lane];

    const int ebase = blockIdx.x * 32 + warp * 4;

    #pragma unroll 1
    for (int it = 0; it < 4; it++) {
        const int e = ebase + it;
        if (e >= E_TOTAL) break;

        if (lane < FDIM) sf[warp][lane] = f[e * FDIM + lane];
        __syncwarp();

        float acc = bb1;
        #pragma unroll
        for (int j = 0; j < FDIM; j++)
            acc = fmaf(sf[warp][j], w1s[lane * FDIM + j], acc);

        float m = acc;
        #pragma unroll
        for (int o = 16; o > 0; o >>= 1) m += __shfl_xor_sync(0xffffffffu, m, o);
        m *= (1.0f / 32.0f);
        float d = acc - m;
        float v = d * d;
        #pragma unroll
        for (int o = 16; o > 0; o >>= 1) v += __shfl_xor_sync(0xffffffffu, v, o);
        v *= (1.0f / 32.0f);
        float y = fmaxf(fmaf(d * rsqrtf(v + LN_EPS), gg1, bbe1), 0.0f);

        sh[warp][lane] = y;
        __syncwarp();

        float acc2 = bb2;
        #pragma unroll
        for (int k = 0; k < HDIM; k++)
            acc2 = fmaf(sh[warp][k], w2s[lane * 33 + k], acc2);

        float m2 = acc2;
        #pragma unroll
        for (int o = 16; o > 0; o >>= 1) m2 += __shfl_xor_sync(0xffffffffu, m2, o);
        m2 *= (1.0f / 32.0f);
        float d2 = acc2 - m2;
        float v2 = d2 * d2;
        #pragma unroll
        for (int o = 16; o > 0; o >>= 1) v2 += __shfl_xor_sync(0xffffffffu, v2, o);
        v2 *= (1.0f / 32.0f);
        float y2 = fmaxf(fmaf(d2 * rsqrtf(v2 + LN_EPS), gg2, bbe2), 0.0f);

        g_h[e * HDIM + lane] = y2;
        __syncwarp();
    }
}

// ---------------------------------------------------------------------------
// Kernel 2: fused r = h @ w3^T + b3, einsum, transposed coalesced epilogue.
// Grid (32 co, 157 tiles); block 128 = 4 warps, lane = ci in main loop.
// Basis staged in smem re-laid-out as [el][di][dd*3+f] (stride 40/edge) so
// the transposed epilogue reads each lane's 9 B-values in 3 vector LDS at
// compile-time offsets. Epilogue: 3 passes (lane -> output column p*32+lane):
// 3 SHFL (r from lane c/3) + 3 LDS + 9 FMA + 3 fully-coalesced STG.32.
// Store wavefronts per edge: 27 -> 9.
// ---------------------------------------------------------------------------
__global__ __launch_bounds__(128, 4) void conv_kernel(
    const float* __restrict__ basis,
    const float* __restrict__ w3,
    const float* __restrict__ b3,
    float* __restrict__ out)
{
    const int co    = blockIdx.x;
    const int ebase = blockIdx.y * TILE_E;
    const int tid   = threadIdx.x;
    const int ci    = tid & 31;
    const int lane  = ci;
    const int warp  = tid >> 5;

    __shared__ float w_s[96 * 36];           // 13.8 KB
    __shared__ float h_s[TILE_E * HDIM];     // 16 KB
    __shared__ float B_s[TILE_E * 40];       // 20 KB, [el][di*12 + dd*3 + f]

    // --- stage w3 slice for this co (contiguous rows) ---
    {
        const float4* src = (const float4*)(w3 + (size_t)co * 96 * 32);
        #pragma unroll
        for (int g = tid; g < 768; g += 128) {
            int row = g >> 3, qi = g & 7;
            *(float4*)&w_s[row * 36 + qi * 4] = src[g];
        }
    }
    const int nE = (E_TOTAL - ebase < TILE_E) ? (E_TOTAL - ebase) : TILE_E;
    // --- stage h tile ---
    {
        const float4* src = (const float4*)(g_h + (size_t)ebase * HDIM);
        const int nf4 = (nE * HDIM) >> 2;
        for (int g = tid; g < nf4; g += 128)
            *(float4*)&h_s[g * 4] = src[g];
    }
    // --- stage basis tile, transposed to [di][dd*3+f] per edge ---
    {
        const float* src = basis + (size_t)ebase * 27;
        const int n = nE * 27;
        for (int g = tid; g < n; g += 128) {
            int el = g / 27, m = g - el * 27;          // m = dd*9 + di*3 + f
            int dd = m / 9;
            int rem = m - dd * 9;
            int di = rem / 3;
            int ff = rem - di * 3;
            B_s[el * 40 + di * 12 + dd * 3 + ff] = src[g];
        }
    }
    __syncthreads();

    // --- per-thread register copy of its 3 w3 rows, packed f32x2 ---
    unsigned long long wpk[3][16];
    #pragma unroll
    for (int ff = 0; ff < 3; ff++) {
        const float* wr = &w_s[(ci * 3 + ff) * 36];
        #pragma unroll
        for (int q = 0; q < 8; q++) {
            float4 t = *(const float4*)&wr[q * 4];
            wpk[ff][2 * q + 0] = pk2(t.x, t.y);
            wpk[ff][2 * q + 1] = pk2(t.z, t.w);
        }
    }
    const int ibase = (co * 32 + ci) * 3;
    const unsigned long long bias0p = pk2(b3[ibase + 0], 0.0f);
    const unsigned long long bias1p = pk2(b3[ibase + 1], 0.0f);
    const unsigned long long bias2p = pk2(b3[ibase + 2], 0.0f);

    // transposed-epilogue constants (edge-independent)
    int srcl[3], dio[3];
    #pragma unroll
    for (int p = 0; p < 3; p++) {
        const int c = p * 32 + lane;
        srcl[p] = c / 3;            // lane holding r for this column
        dio[p]  = (c - srcl[p] * 3) * 12;   // di*12 smem offset
    }

    float* const obase = out + (size_t)ebase * 9216 + (size_t)co * 288 + lane;

    #pragma unroll 1
    for (int el = warp * 32; el < (warp + 1) * 32; el++) {
        if (el >= nE) break;                      // warp-uniform

        unsigned long long a0 = bias0p;
        unsigned long long a1 = bias1p;
        unsigned long long a2 = bias2p;

        const ulonglong2* hp = (const ulonglong2*)&h_s[el * HDIM];
        #pragma unroll
        for (int q = 0; q < 8; q++) {
            ulonglong2 hv = hp[q];                // LDS.128 -> two b64 pairs
            fma2(a0, hv.x, wpk[0][2 * q]);  fma2(a0, hv.y, wpk[0][2 * q + 1]);
            fma2(a1, hv.x, wpk[1][2 * q]);  fma2(a1, hv.y, wpk[1][2 * q + 1]);
            fma2(a2, hv.x, wpk[2][2 * q]);  fma2(a2, hv.y, wpk[2][2 * q + 1]);
        }
        float r0, r0b, r1, r1b, r2, r2b;
        upk2(a0, r0, r0b);  upk2(a1, r1, r1b);  upk2(a2, r2, r2b);
        r0 += r0b;  r1 += r1b;  r2 += r2b;

        // --- transposed epilogue: coalesced stores ---
        const float* Bd = &B_s[el * 40];
        float* op = obase + (size_t)el * 9216;

        #pragma unroll
        for (int p = 0; p < 3; p++) {
            const float ra = __shfl_sync(0xffffffffu, r0, srcl[p]);
            const float rb = __shfl_sync(0xffffffffu, r1, srcl[p]);
            const float rc = __shfl_sync(0xffffffffu, r2, srcl[p]);
            const float* bq = Bd + dio[p];        // 3 distinct addrs/warp
            float4 t0 = *(const float4*)bq;       // dd0:f0,f1,f2  dd1:f0
            float4 t1 = *(const float4*)(bq + 4); // dd1:f1,f2     dd2:f0,f1
            float  t2 = bq[8];                    // dd2:f2
            float v0 = fmaf(rc, t0.z, fmaf(rb, t0.y, ra * t0.x));
            float v1 = fmaf(rc, t1.y, fmaf(rb, t1.x, ra * t0.w));
            float v2 = fmaf(rc, t2,   fmaf(rb, t1.w, ra * t1.z));
            op[p * 32 + 0]   = v0;                // coalesced 128B per warp
            op[p * 32 + 96]  = v1;
            op[p * 32 + 192] = v2;
        }
    }
}

// ---------------------------------------------------------------------------
extern "C" void kernel_launch(void* const* d_in, const int* in_sizes, int n_in,
                              void* d_out, int out_size)
{
    const float* f     = (const float*)d_in[0];
    const float* basis = (const float*)d_in[1];
    const float* w1    = (const float*)d_in[2];
    const float* b1    = (const float*)d_in[3];
    const float* g1    = (const float*)d_in[4];
    const float* be1   = (const float*)d_in[5];
    const float* w2    = (const float*)d_in[6];
    const float* b2    = (const float*)d_in[7];
    const float* g2    = (const float*)d_in[8];
    const float* be2   = (const float*)d_in[9];
    const float* w3    = (const float*)d_in[10];
    const float* b3    = (const float*)d_in[11];
    float* out = (float*)d_out;

    mlp_kernel<<<(E_TOTAL + 31) / 32, 256>>>(f, w1, b1, g1, be1, w2, b2, g2, be2);

    dim3 grid(32, (E_TOTAL + TILE_E - 1) / TILE_E);
    conv_kernel<<<grid, 128>>>(basis, w3, b3, out);
}

// round 14
// speedup vs baseline: 1.3838x; 1.3838x over previous
#include <cuda_runtime.h>

#define E_TOTAL 20000
#define FDIM 17
#define HDIM 32
#define TILE_E 128
#define LN_EPS 1e-5f

__device__ float g_h[E_TOTAL * HDIM];

// ---------- packed fp32x2 helpers (Blackwell dual-FP32) ----------
__device__ __forceinline__ unsigned long long pk2(float x, float y) {
    unsigned long long r;
    asm("mov.b64 %0, {%1, %2};" : "=l"(r) : "f"(x), "f"(y));
    return r;
}
__device__ __forceinline__ void upk2(unsigned long long v, float& x, float& y) {
    asm("mov.b64 {%0, %1}, %2;" : "=f"(x), "=f"(y) : "l"(v));
}
__device__ __forceinline__ void fma2(unsigned long long& d,
                                     unsigned long long a, unsigned long long b) {
    asm("fma.rn.f32x2 %0, %1, %2, %0;" : "+l"(d) : "l"(a), "l"(b));
}

// ---------------------------------------------------------------------------
// Kernel 1: radial MLP  f[E,17] -> h[E,32]   (4 edges per warp)
// Ends with griddepcontrol.launch_dependents (PDL release of g_h stores).
// ---------------------------------------------------------------------------
__global__ __launch_bounds__(256) void mlp_kernel(
    const float* __restrict__ f,
    const float* __restrict__ w1, const float* __restrict__ b1,
    const float* __restrict__ g1, const float* __restrict__ be1,
    const float* __restrict__ w2, const float* __restrict__ b2,
    const float* __restrict__ g2, const float* __restrict__ be2)
{
    const int tid  = threadIdx.x;
    const int warp = tid >> 5;
    const int lane = tid & 31;

    __shared__ float w1s[32 * FDIM];      // 17 odd => conflict-free
    __shared__ float w2s[32 * 33];        // padded
    __shared__ float sf[8][FDIM];
    __shared__ float sh[8][HDIM];

    for (int i = tid; i < 32 * FDIM; i += 256) w1s[i] = w1[i];
    for (int i = tid; i < 32 * 32;  i += 256) w2s[(i >> 5) * 33 + (i & 31)] = w2[i];
    __syncthreads();

    const float bb1 = b1[lane], gg1 = g1[lane], bbe1 = be1[lane];
    const float bb2 = b2[lane], gg2 = g2[lane], bbe2 = be2[lane];

    const int ebase = blockIdx.x * 32 + warp * 4;

    #pragma unroll 1
    for (int it = 0; it < 4; it++) {
        const int e = ebase + it;
        if (e >= E_TOTAL) break;

        if (lane < FDIM) sf[warp][lane] = f[e * FDIM + lane];
        __syncwarp();

        float acc = bb1;
        #pragma unroll
        for (int j = 0; j < FDIM; j++)
            acc = fmaf(sf[warp][j], w1s[lane * FDIM + j], acc);

        float m = acc;
        #pragma unroll
        for (int o = 16; o > 0; o >>= 1) m += __shfl_xor_sync(0xffffffffu, m, o);
        m *= (1.0f / 32.0f);
        float d = acc - m;
        float v = d * d;
        #pragma unroll
        for (int o = 16; o > 0; o >>= 1) v += __shfl_xor_sync(0xffffffffu, v, o);
        v *= (1.0f / 32.0f);
        float y = fmaxf(fmaf(d * rsqrtf(v + LN_EPS), gg1, bbe1), 0.0f);

        sh[warp][lane] = y;
        __syncwarp();

        float acc2 = bb2;
        #pragma unroll
        for (int k = 0; k < HDIM; k++)
            acc2 = fmaf(sh[warp][k], w2s[lane * 33 + k], acc2);

        float m2 = acc2;
        #pragma unroll
        for (int o = 16; o > 0; o >>= 1) m2 += __shfl_xor_sync(0xffffffffu, m2, o);
        m2 *= (1.0f / 32.0f);
        float d2 = acc2 - m2;
        float v2 = d2 * d2;
        #pragma unroll
        for (int o = 16; o > 0; o >>= 1) v2 += __shfl_xor_sync(0xffffffffu, v2, o);
        v2 *= (1.0f / 32.0f);
        float y2 = fmaxf(fmaf(d2 * rsqrtf(v2 + LN_EPS), gg2, bbe2), 0.0f);

        g_h[e * HDIM + lane] = y2;
        __syncwarp();
    }

    // PDL release: this thread's g_h writes are visible to dependents' wait.
    asm volatile("griddepcontrol.launch_dependents;");
}

// ---------------------------------------------------------------------------
// Kernel 2 (R12-proven body): fused r = h @ w3^T + b3, einsum, direct write.
// Staging reordered: w3 + basis (independent of mlp) BEFORE griddepcontrol.wait,
// h tile after — so under PDL the preamble overlaps the mlp kernel.
// ---------------------------------------------------------------------------
__global__ __launch_bounds__(128, 4) void conv_kernel(
    const float* __restrict__ basis,
    const float* __restrict__ w3,
    const float* __restrict__ b3,
    float* __restrict__ out)
{
    const int co    = blockIdx.x;
    const int ebase = blockIdx.y * TILE_E;
    const int tid   = threadIdx.x;
    const int ci    = tid & 31;
    const int warp  = tid >> 5;

    __shared__ float w_s[96 * 36];
    __shared__ float h_s[TILE_E * HDIM];
    __shared__ float B_s[TILE_E * 28];      // stride 28 (112B, 16B-aligned rows)

    // --- stage w3 slice for this co (independent of mlp) ---
    {
        const float4* src = (const float4*)(w3 + (size_t)co * 96 * 32);
        #pragma unroll
        for (int g = tid; g < 768; g += 128) {
            int row = g >> 3, qi = g & 7;
            *(float4*)&w_s[row * 36 + qi * 4] = src[g];
        }
    }
    const int nE = (E_TOTAL - ebase < TILE_E) ? (E_TOTAL - ebase) : TILE_E;
    // --- stage basis tile (independent of mlp) ---
    {
        const float* src = basis + (size_t)ebase * 27;
        const int n = nE * 27;
        for (int g = tid; g < n; g += 128) {
            int el = g / 27, j = g - el * 27;
            B_s[el * 28 + j] = src[g];
        }
    }

    // PDL acquire: g_h (written by mlp) is safe to read after this.
    asm volatile("griddepcontrol.wait;");

    // --- stage h tile ---
    {
        const float4* src = (const float4*)(g_h + (size_t)ebase * HDIM);
        const int nf4 = (nE * HDIM) >> 2;
        for (int g = tid; g < nf4; g += 128)
            *(float4*)&h_s[g * 4] = src[g];
    }
    __syncthreads();

    // --- per-thread register copy of its 3 w3 rows, packed f32x2 ---
    unsigned long long wpk[3][16];
    #pragma unroll
    for (int ff = 0; ff < 3; ff++) {
        const float* wr = &w_s[(ci * 3 + ff) * 36];
        #pragma unroll
        for (int q = 0; q < 8; q++) {
            float4 t = *(const float4*)&wr[q * 4];
            wpk[ff][2 * q + 0] = pk2(t.x, t.y);
            wpk[ff][2 * q + 1] = pk2(t.z, t.w);
        }
    }
    const int ibase = (co * 32 + ci) * 3;
    const unsigned long long bias0p = pk2(b3[ibase + 0], 0.0f);
    const unsigned long long bias1p = pk2(b3[ibase + 1], 0.0f);
    const unsigned long long bias2p = pk2(b3[ibase + 2], 0.0f);

    #pragma unroll 1
    for (int el = warp * 32; el < (warp + 1) * 32; el++) {
        if (el >= nE) break;                      // warp-uniform

        unsigned long long a0 = bias0p;
        unsigned long long a1 = bias1p;
        unsigned long long a2 = bias2p;

        const ulonglong2* hp = (const ulonglong2*)&h_s[el * HDIM];
        #pragma unroll
        for (int q = 0; q < 8; q++) {
            ulonglong2 hv = hp[q];                // LDS.128 -> two b64 pairs
            fma2(a0, hv.x, wpk[0][2 * q]);  fma2(a0, hv.y, wpk[0][2 * q + 1]);
            fma2(a1, hv.x, wpk[1][2 * q]);  fma2(a1, hv.y, wpk[1][2 * q + 1]);
            fma2(a2, hv.x, wpk[2][2 * q]);  fma2(a2, hv.y, wpk[2][2 * q + 1]);
        }
        float r0, r0b, r1, r1b, r2, r2b;
        upk2(a0, r0, r0b);  upk2(a1, r1, r1b);  upk2(a2, r2, r2b);
        r0 += r0b;  r1 += r1b;  r2 += r2b;

        // --- streaming epilogue: consume basis float4s immediately ---
        const float4* Bp4 = (const float4*)&B_s[el * 28];
        float o0, o1, o2, o3, o4, o5, o6, o7, o8;
        {
            float4 a = Bp4[0];                                  // m 0..3
            o0 = fmaf(r2, a.z, fmaf(r1, a.y, r0 * a.x));
            o1 = r0 * a.w;
            float4 b = Bp4[1];                                  // m 4..7
            o1 = fmaf(r2, b.y, fmaf(r1, b.x, o1));
            o2 = fmaf(r1, b.w, r0 * b.z);
            float4 c = Bp4[2];                                  // m 8..11
            o2 = fmaf(r2, c.x, o2);
            o3 = fmaf(r2, c.w, fmaf(r1, c.z, r0 * c.y));
            float4 d = Bp4[3];                                  // m 12..15
            o4 = fmaf(r2, d.z, fmaf(r1, d.y, r0 * d.x));
            o5 = r0 * d.w;
            float4 e4 = Bp4[4];                                 // m 16..19
            o5 = fmaf(r2, e4.y, fmaf(r1, e4.x, o5));
            o6 = fmaf(r1, e4.w, r0 * e4.z);
            float4 f4 = Bp4[5];                                 // m 20..23
            o6 = fmaf(r2, f4.x, o6);
            o7 = fmaf(r2, f4.w, fmaf(r1, f4.z, r0 * f4.y));
            float4 g4 = Bp4[6];                                 // m 24..26 (+pad)
            o8 = fmaf(r2, g4.z, fmaf(r1, g4.y, r0 * g4.x));
        }

        float* op = out + (size_t)(ebase + el) * 9216 + (size_t)(co * 3) * 96 + ci * 3;
        op[0]   = o0;  op[1]   = o1;  op[2]   = o2;
        op[96]  = o3;  op[97]  = o4;  op[98]  = o5;
        op[192] = o6;  op[193] = o7;  op[194] = o8;
    }
}

// ---------------------------------------------------------------------------
extern "C" void kernel_launch(void* const* d_in, const int* in_sizes, int n_in,
                              void* d_out, int out_size)
{
    const float* f     = (const float*)d_in[0];
    const float* basis = (const float*)d_in[1];
    const float* w1    = (const float*)d_in[2];
    const float* b1    = (const float*)d_in[3];
    const float* g1    = (const float*)d_in[4];
    const float* be1   = (const float*)d_in[5];
    const float* w2    = (const float*)d_in[6];
    const float* b2    = (const float*)d_in[7];
    const float* g2    = (const float*)d_in[8];
    const float* be2   = (const float*)d_in[9];
    const float* w3    = (const float*)d_in[10];
    const float* b3    = (const float*)d_in[11];
    float* out = (float*)d_out;

    mlp_kernel<<<(E_TOTAL + 31) / 32, 256>>>(f, w1, b1, g1, be1, w2, b2, g2, be2);

    dim3 grid(32, (E_TOTAL + TILE_E - 1) / TILE_E);

    // PDL launch of conv: may start while mlp runs; conv's griddepcontrol.wait
    // gates the g_h reads. Fall back to a plain launch if the attribute is
    // rejected (e.g., unsupported under capture) — identical to R12 then.
    cudaLaunchConfig_t cfg = {};
    cfg.gridDim  = grid;
    cfg.blockDim = dim3(128, 1, 1);
    cfg.dynamicSmemBytes = 0;
    cfg.stream = 0;
    cudaLaunchAttribute attr[1];
    attr[0].id = cudaLaunchAttributeProgrammaticStreamSerialization;
    attr[0].val.programmaticStreamSerializationAllowed = 1;
    cfg.attrs = attr;
    cfg.numAttrs = 1;

    cudaError_t err = cudaLaunchKernelEx(&cfg, conv_kernel, basis, w3, b3, out);
    if (err != cudaSuccess) {
        conv_kernel<<<grid, 128>>>(basis, w3, b3, out);
    }
}